// round 1
// baseline (speedup 1.0000x reference)
#include <cuda_runtime.h>
#include <cstdint>

#define M_DIM 8192      // B*S = 4*2048
#define K_DIM 4096      // DIN
#define N_DIM 11008     // DOUT

// 180 MB scratch for transformed+transposed weight (allocation-free rule:
// __device__ global array).
__device__ float g_wt[(size_t)K_DIM * N_DIM];
__device__ int g_mask_mode;   // 0 = uint8 bool, 1 = int32, 2 = float32

// ---------------------------------------------------------------------------
// Mask dtype detection. Reads only in_sizes[3]/4 words (safe even if the
// buffer is 1 byte/elem). uint8-bool layout yields words with 0x01 bytes in
// upper positions (not in {0,1,0x3F800000}); float32 yields 0x3F800000;
// int32 yields only {0,1}.
// ---------------------------------------------------------------------------
__global__ void detect_mask_mode(const unsigned int* __restrict__ w, long nwords) {
    __shared__ int s_byte, s_float;
    if (threadIdx.x == 0) { s_byte = 0; s_float = 0; }
    __syncthreads();
    int loc_byte = 0, loc_float = 0;
    for (long i = threadIdx.x; i < nwords; i += blockDim.x) {
        unsigned int v = w[i];
        if (v == 0x3F800000u)      loc_float = 1;
        else if (v != 0u && v != 1u) loc_byte = 1;
    }
    if (loc_byte)  atomicOr(&s_byte, 1);
    if (loc_float) atomicOr(&s_float, 1);
    __syncthreads();
    if (threadIdx.x == 0)
        g_mask_mode = s_byte ? 0 : (s_float ? 2 : 1);
}

// ---------------------------------------------------------------------------
// Fused weight transform + transpose: W[n,k] -> W_eff^T[k,n]
// W_eff = mask ? w * 1.0 : sign(w) * binary_scale
// ---------------------------------------------------------------------------
__global__ void pack_weights(const float* __restrict__ w,
                             const void* __restrict__ mask,
                             const float* __restrict__ bscale) {
    __shared__ float tile[32][33];
    const int n0 = blockIdx.x * 32;
    const int k0 = blockIdx.y * 32;
    const float scale = bscale[0];
    const int mode = g_mask_mode;
    const int tx = threadIdx.x, ty = threadIdx.y;

#pragma unroll
    for (int i = 0; i < 4; i++) {
        int n = n0 + ty + i * 8;
        int k = k0 + tx;
        size_t idx = (size_t)n * K_DIM + k;
        float v = w[idx];
        bool m;
        if (mode == 0)      m = ((const unsigned char*)mask)[idx] != 0;
        else if (mode == 1) m = ((const int*)mask)[idx] != 0;
        else                m = ((const float*)mask)[idx] != 0.0f;
        float s = (v > 0.0f) ? scale : ((v < 0.0f) ? -scale : 0.0f);
        tile[ty + i * 8][tx] = m ? v : s;
    }
    __syncthreads();
#pragma unroll
    for (int i = 0; i < 4; i++) {
        int k = k0 + ty + i * 8;
        int n = n0 + tx;
        g_wt[(size_t)k * N_DIM + n] = tile[tx][ty + i * 8];
    }
}

// ---------------------------------------------------------------------------
// SGEMM: C[M,N] = A[M,K] @ Wt[K,N] + bias
// 128x128 block tile, BK=8, 256 threads, 8x8 per-thread micro-tile.
// ---------------------------------------------------------------------------
__global__ void __launch_bounds__(256)
sgemm_bias(const float* __restrict__ A,
           const float* __restrict__ bias,
           float* __restrict__ C) {
    __shared__ float As[8][128];   // [k][m], transposed A tile
    __shared__ float Bs[8][128];   // [k][n]

    const int bx = blockIdx.x;     // n tile
    const int by = blockIdx.y;     // m tile
    const int tid = threadIdx.x;
    const int tx = tid % 16;       // n micro
    const int ty = tid / 16;       // m micro

    // A tile load mapping: 128 rows x 8 k -> one float4 per thread along k
    const int aRow  = tid >> 1;          // 0..127
    const int aCol4 = (tid & 1) * 4;     // 0 or 4
    // B tile load mapping: 8 k-rows x 128 n -> one float4 per thread along n
    const int bRow  = tid >> 5;          // 0..7
    const int bCol4 = (tid & 31) * 4;    // 0..124

    const float* Aptr = A + (size_t)(by * 128) * K_DIM;
    const float* Bptr = g_wt + bx * 128;

    float acc[8][8];
#pragma unroll
    for (int i = 0; i < 8; i++)
#pragma unroll
        for (int j = 0; j < 8; j++) acc[i][j] = 0.0f;

    for (int k0 = 0; k0 < K_DIM; k0 += 8) {
        float4 av = *(const float4*)(Aptr + (size_t)aRow * K_DIM + k0 + aCol4);
        As[aCol4 + 0][aRow] = av.x;
        As[aCol4 + 1][aRow] = av.y;
        As[aCol4 + 2][aRow] = av.z;
        As[aCol4 + 3][aRow] = av.w;

        float4 bv = *(const float4*)(Bptr + (size_t)(k0 + bRow) * N_DIM + bCol4);
        *(float4*)&Bs[bRow][bCol4] = bv;
        __syncthreads();

#pragma unroll
        for (int kk = 0; kk < 8; kk++) {
            float a[8], b[8];
            *(float4*)&a[0] = *(const float4*)&As[kk][ty * 8];
            *(float4*)&a[4] = *(const float4*)&As[kk][ty * 8 + 4];
            *(float4*)&b[0] = *(const float4*)&Bs[kk][tx * 8];
            *(float4*)&b[4] = *(const float4*)&Bs[kk][tx * 8 + 4];
#pragma unroll
            for (int i = 0; i < 8; i++)
#pragma unroll
                for (int j = 0; j < 8; j++)
                    acc[i][j] += a[i] * b[j];
        }
        __syncthreads();
    }

    const int m0 = by * 128 + ty * 8;
    const int n0 = bx * 128 + tx * 8;
    float4 bv0 = *(const float4*)(bias + n0);
    float4 bv1 = *(const float4*)(bias + n0 + 4);
#pragma unroll
    for (int i = 0; i < 8; i++) {
        float* crow = C + (size_t)(m0 + i) * N_DIM + n0;
        float4 o0, o1;
        o0.x = acc[i][0] + bv0.x; o0.y = acc[i][1] + bv0.y;
        o0.z = acc[i][2] + bv0.z; o0.w = acc[i][3] + bv0.w;
        o1.x = acc[i][4] + bv1.x; o1.y = acc[i][5] + bv1.y;
        o1.z = acc[i][6] + bv1.z; o1.w = acc[i][7] + bv1.w;
        *(float4*)crow       = o0;
        *(float4*)(crow + 4) = o1;
    }
}

// ---------------------------------------------------------------------------
extern "C" void kernel_launch(void* const* d_in, const int* in_sizes, int n_in,
                              void* d_out, int out_size) {
    const float* x      = (const float*)d_in[0];   // [8192, 4096]
    const float* weight = (const float*)d_in[1];   // [11008, 4096]
    const float* bias   = (const float*)d_in[2];   // [11008]
    const void*  mask   = d_in[3];                 // [11008, 4096] dtype unknown
    const float* bscale = (const float*)d_in[4];   // [1,1]
    float* out = (float*)d_out;

    // 1. Detect mask storage dtype (reads only bytes guaranteed to exist).
    long nwords = (long)in_sizes[3] / 4;
    if (nwords > (1L << 21)) nwords = 1L << 21;
    detect_mask_mode<<<1, 1024>>>((const unsigned int*)mask, nwords);

    // 2. Transform + transpose weights into g_wt.
    dim3 pgrid(N_DIM / 32, K_DIM / 32);
    pack_weights<<<pgrid, dim3(32, 8)>>>(weight, mask, bscale);

    // 3. GEMM + bias.
    dim3 ggrid(N_DIM / 128, M_DIM / 128);
    sgemm_bias<<<ggrid, 256>>>(x, bias, out);
}

// round 3
// speedup vs baseline: 2.8870x; 2.8870x over previous
#include <cuda_runtime.h>
#include <cuda_fp16.h>
#include <cstdint>

#define MD 8192
#define KD 4096
#define ND 11008
#define K3 (3*KD)          // 12288
#define BM 256
#define BN 128
#define BK 64
#define NIT (K3/BK)        // 192
#define STAGES 3
#define STAGE_BYTES ((BM+BN)*128)        // 49152
#define SMEM_BYTES (STAGES*STAGE_BYTES)  // 147456
#define NT (ND/BN)         // 86 n-tiles
#define MT (MD/BM)         // 32 m-tiles

// ---------------- scratch (__device__ globals; allocation-free rule) -------
__device__ __align__(256) __half g_A[(size_t)MD * K3];   // [M, 3K] = [Xhi|Xhi|Xlo]
__device__ __align__(256) __half g_B[(size_t)ND * K3];   // [N, 3K] = [Whi|Wlo|Whi]
__device__ int g_fbyte;
__device__ int g_ffloat;

// ---------------- helpers ----------------------------------------------------
__device__ __forceinline__ uint32_t smem_u32(const void* p) {
    uint32_t a;
    asm("{ .reg .u64 t; cvta.to.shared.u64 t, %1; cvt.u32.u64 %0, t; }"
        : "=r"(a) : "l"(p));
    return a;
}
// row*128B tiles, 8 x 16B chunks, SW128 XOR swizzle (conflict-free ldmatrix)
__device__ __forceinline__ uint32_t phys(uint32_t r, uint32_t c) {
    return r * 128u + ((c ^ (r & 7u)) << 4);
}
__device__ __forceinline__ void cp_async16(uint32_t s, const void* g) {
    asm volatile("cp.async.cg.shared.global [%0], [%1], 16;" :: "r"(s), "l"(g));
}
__device__ __forceinline__ void ldsm_x4(uint32_t addr, uint32_t& r0, uint32_t& r1,
                                        uint32_t& r2, uint32_t& r3) {
    asm volatile("ldmatrix.sync.aligned.m8n8.x4.shared.b16 {%0,%1,%2,%3}, [%4];"
                 : "=r"(r0), "=r"(r1), "=r"(r2), "=r"(r3) : "r"(addr));
}
__device__ __forceinline__ void hmma(float* c, const uint32_t* a, const uint32_t* b) {
    asm volatile(
        "mma.sync.aligned.m16n8k16.row.col.f32.f16.f16.f32 "
        "{%0,%1,%2,%3}, {%4,%5,%6,%7}, {%8,%9}, {%0,%1,%2,%3};"
        : "+f"(c[0]), "+f"(c[1]), "+f"(c[2]), "+f"(c[3])
        : "r"(a[0]), "r"(a[1]), "r"(a[2]), "r"(a[3]), "r"(b[0]), "r"(b[1]));
}

// ---------------- mask dtype detection (parallel) ---------------------------
__global__ void zero_flags() { g_fbyte = 0; g_ffloat = 0; }

__global__ void detect_mask_mode(const unsigned int* __restrict__ w, long nwords) {
    int lb = 0, lf = 0;
    long stride = (long)gridDim.x * blockDim.x;
    for (long i = (long)blockIdx.x * blockDim.x + threadIdx.x; i < nwords; i += stride) {
        unsigned int v = w[i];
        if (v == 0x3F800000u)        lf = 1;
        else if (v != 0u && v != 1u) lb = 1;
    }
    if (__syncthreads_or(lb)) { if (threadIdx.x == 0) atomicOr(&g_fbyte, 1); }
    if (__syncthreads_or(lf)) { if (threadIdx.x == 0) atomicOr(&g_ffloat, 1); }
}

// ---------------- conversions ------------------------------------------------
__device__ __forceinline__ unsigned short h_bits(__half h) {
    return *reinterpret_cast<unsigned short*>(&h);
}

// A' = [Xhi | Xhi | Xlo]
__global__ void __launch_bounds__(256) convert_x(const float* __restrict__ x) {
    size_t idx = (size_t)blockIdx.x * blockDim.x + threadIdx.x;
    int m = (int)(idx / (KD / 4));
    int k = (int)(idx % (KD / 4)) * 4;
    float4 v = *(const float4*)(x + (size_t)m * KD + k);
    float f[4] = {v.x, v.y, v.z, v.w};
    unsigned short hb[4], lb[4];
#pragma unroll
    for (int j = 0; j < 4; j++) {
        __half h = __float2half_rn(f[j]);
        hb[j] = h_bits(h);
        lb[j] = h_bits(__float2half_rn(f[j] - __half2float(h)));
    }
    ushort4 hi = make_ushort4(hb[0], hb[1], hb[2], hb[3]);
    ushort4 lo = make_ushort4(lb[0], lb[1], lb[2], lb[3]);
    ushort4* row = (ushort4*)(g_A + (size_t)m * K3);
    row[k / 4]            = hi;
    row[(KD + k) / 4]     = hi;
    row[(2 * KD + k) / 4] = lo;
}

// B' = [Whi | Wlo | Whi],  W_sim = mask ? w : sign(w)*scale
__global__ void __launch_bounds__(256) convert_w(const float* __restrict__ w,
                                                 const void* __restrict__ mask,
                                                 const float* __restrict__ bscale) {
    size_t idx = (size_t)blockIdx.x * blockDim.x + threadIdx.x;
    int n = (int)(idx / (KD / 4));
    int k = (int)(idx % (KD / 4)) * 4;
    size_t base = (size_t)n * KD + k;
    float4 v = *(const float4*)(w + base);
    const float scale = bscale[0];
    const int mode = g_fbyte ? 0 : (g_ffloat ? 2 : 1);

    bool mk[4];
    if (mode == 0) {
        uchar4 mv = *(const uchar4*)((const unsigned char*)mask + base);
        mk[0] = mv.x != 0; mk[1] = mv.y != 0; mk[2] = mv.z != 0; mk[3] = mv.w != 0;
    } else if (mode == 1) {
        int4 mv = *(const int4*)((const int*)mask + base);
        mk[0] = mv.x != 0; mk[1] = mv.y != 0; mk[2] = mv.z != 0; mk[3] = mv.w != 0;
    } else {
        float4 mv = *(const float4*)((const float*)mask + base);
        mk[0] = mv.x != 0.f; mk[1] = mv.y != 0.f; mk[2] = mv.z != 0.f; mk[3] = mv.w != 0.f;
    }

    float f[4] = {v.x, v.y, v.z, v.w};
    unsigned short hb[4], lb[4];
#pragma unroll
    for (int j = 0; j < 4; j++) {
        float s = (f[j] > 0.f) ? scale : ((f[j] < 0.f) ? -scale : 0.f);
        float ws = mk[j] ? f[j] : s;
        __half h = __float2half_rn(ws);
        hb[j] = h_bits(h);
        lb[j] = h_bits(__float2half_rn(ws - __half2float(h)));
    }
    ushort4 hi = make_ushort4(hb[0], hb[1], hb[2], hb[3]);
    ushort4 lo = make_ushort4(lb[0], lb[1], lb[2], lb[3]);
    ushort4* row = (ushort4*)(g_B + (size_t)n * K3);
    row[k / 4]            = hi;
    row[(KD + k) / 4]     = lo;
    row[(2 * KD + k) / 4] = hi;
}

// ---------------- GEMM: C[M,N] = A' @ B'^T + bias ---------------------------
// 256x128 CTA tile, BK=64, 8 warps (4x2), 64x64 warp tiles, mma.m16n8k16 fp16,
// 3-stage cp.async pipeline, SW128-swizzled smem, conflict-free ldmatrix.
__global__ void __launch_bounds__(256, 1)
gemm_hmma(const float* __restrict__ bias, float* __restrict__ C) {
    extern __shared__ char smem[];
    const uint32_t sb = smem_u32(smem);
    const int tid  = threadIdx.x;
    const int lane = tid & 31;
    const int warp = tid >> 5;
    const int wm = warp >> 1;          // 0..3
    const int wn = warp & 1;           // 0..1

    // CTA raster swizzle: groups of 8 n-tiles, m-major inside group (L2 reuse)
    int bid = blockIdx.x;
    int bm, bn;
    const int FULLG = (NT / 8) * 8 * MT;        // 80*32 = 2560
    if (bid < FULLG) {
        int g = bid >> 8;                        // /256
        int r = bid & 255;
        bn = g * 8 + (r & 7);
        bm = r >> 3;
    } else {
        int r = bid - FULLG;
        bn = (NT / 8) * 8 + r % (NT % 8 == 0 ? 1 : NT % 8);
        bm = r / (NT % 8 == 0 ? 1 : NT % 8);
    }
    const int m0 = bm * BM, n0 = bn * BN;

    const __half* gA = g_A + (size_t)m0 * K3;
    const __half* gB = g_B + (size_t)n0 * K3;

    float acc[4][8][4];
#pragma unroll
    for (int i = 0; i < 4; i++)
#pragma unroll
        for (int j = 0; j < 8; j++)
#pragma unroll
            for (int t = 0; t < 4; t++) acc[i][j][t] = 0.f;

    // ---- stage loader ----
    auto load_stage = [&](int st, int it) {
        const uint32_t Ast = sb + st * STAGE_BYTES;
        const uint32_t Bst = Ast + BM * 128;
        const size_t koff = (size_t)it * BK;
#pragma unroll
        for (int i = 0; i < 8; i++) {            // A: 256 rows x 8 chunks
            int ch = tid + i * 256;
            uint32_t r = ch >> 3, c = ch & 7;
            cp_async16(Ast + phys(r, c), gA + (size_t)r * K3 + koff + c * 8);
        }
#pragma unroll
        for (int i = 0; i < 4; i++) {            // B: 128 rows x 8 chunks
            int ch = tid + i * 256;
            uint32_t r = ch >> 3, c = ch & 7;
            cp_async16(Bst + phys(r, c), gB + (size_t)r * K3 + koff + c * 8);
        }
        asm volatile("cp.async.commit_group;" ::: "memory");
    };

    load_stage(0, 0);
    load_stage(1, 1);

    const uint32_t lrow = lane & 15;             // ldmatrix row within 16
    const uint32_t lhik = lane >> 4;             // 0: k-lo 8, 1: k-hi 8

    for (int it = 0; it < NIT; it++) {
        asm volatile("cp.async.wait_group 1;" ::: "memory");
        __syncthreads();

        if (it + 2 < NIT) load_stage((it + 2) % STAGES, it + 2);
        else              asm volatile("cp.async.commit_group;" ::: "memory");

        const uint32_t Ast = sb + (it % STAGES) * STAGE_BYTES;
        const uint32_t Bst = Ast + BM * 128;

#pragma unroll
        for (int ks = 0; ks < 4; ks++) {         // 4 x k16 within BK=64
            uint32_t a[4][4], b[8][2];
#pragma unroll
            for (int mi = 0; mi < 4; mi++) {
                uint32_t r = wm * 64 + mi * 16 + lrow;
                ldsm_x4(Ast + phys(r, ks * 2 + lhik),
                        a[mi][0], a[mi][1], a[mi][2], a[mi][3]);
            }
#pragma unroll
            for (int nj = 0; nj < 4; nj++) {
                uint32_t r = wn * 64 + nj * 16 + lrow;
                uint32_t r0, r1, r2, r3;
                ldsm_x4(Bst + phys(r, ks * 2 + lhik), r0, r1, r2, r3);
                b[2 * nj][0] = r0;     b[2 * nj][1] = r2;
                b[2 * nj + 1][0] = r1; b[2 * nj + 1][1] = r3;
            }
#pragma unroll
            for (int mi = 0; mi < 4; mi++)
#pragma unroll
                for (int nf = 0; nf < 8; nf++)
                    hmma(acc[mi][nf], a[mi], b[nf]);
        }
    }

    // ---- epilogue: bias + store fp32 ----
    const int mb = m0 + wm * 64;
    const int nb = n0 + wn * 64;
#pragma unroll
    for (int mi = 0; mi < 4; mi++) {
#pragma unroll
        for (int nf = 0; nf < 8; nf++) {
            int row = mb + mi * 16 + (lane >> 2);
            int col = nb + nf * 8 + (lane & 3) * 2;
            float2 bv = *(const float2*)(bias + col);
            float2 o0 = {acc[mi][nf][0] + bv.x, acc[mi][nf][1] + bv.y};
            float2 o1 = {acc[mi][nf][2] + bv.x, acc[mi][nf][3] + bv.y};
            *(float2*)(C + (size_t)row * ND + col)       = o0;
            *(float2*)(C + (size_t)(row + 8) * ND + col) = o1;
        }
    }
}

// ---------------------------------------------------------------------------
extern "C" void kernel_launch(void* const* d_in, const int* in_sizes, int n_in,
                              void* d_out, int out_size) {
    const float* x      = (const float*)d_in[0];
    const float* weight = (const float*)d_in[1];
    const float* bias   = (const float*)d_in[2];
    const void*  mask   = d_in[3];
    const float* bscale = (const float*)d_in[4];
    float* out = (float*)d_out;

    zero_flags<<<1, 1>>>();
    long nwords = (long)in_sizes[3] / 4;
    detect_mask_mode<<<512, 256>>>((const unsigned int*)mask, nwords);

    convert_x<<<(MD * (KD / 4)) / 256, 256>>>(x);
    convert_w<<<(ND * (KD / 4)) / 256, 256>>>(weight, mask, bscale);

    static int smem_set = 0;
    if (!smem_set) {
        cudaFuncSetAttribute(gemm_hmma, cudaFuncAttributeMaxDynamicSharedMemorySize,
                             SMEM_BYTES);
        smem_set = 1;
    }
    gemm_hmma<<<NT * MT, 256, SMEM_BYTES>>>(bias, out);
}

// round 4
// speedup vs baseline: 2.9004x; 1.0046x over previous
#include <cuda_runtime.h>
#include <cuda_fp16.h>
#include <cstdint>

#define MD 8192
#define KD 4096
#define ND 11008
#define K2 (2*KD)          // stored columns: [hi | lo]
#define NIT 192            // logical k-iters: 3 segments x 64
#define BM 256
#define BN 128
#define BK 64
#define STAGES 4
#define STAGE_BYTES ((BM+BN)*128)        // 49152
#define SMEM_BYTES (STAGES*STAGE_BYTES)  // 196608
#define NT (ND/BN)         // 86
#define MT (MD/BM)         // 32

// ---------------- scratch (__device__ globals; allocation-free rule) -------
__device__ __align__(256) __half g_A[(size_t)MD * K2];   // [M, 2K] = [Xhi|Xlo]
__device__ __align__(256) __half g_B[(size_t)ND * K2];   // [N, 2K] = [Whi|Wlo]

// ---------------- helpers ----------------------------------------------------
__device__ __forceinline__ uint32_t smem_u32(const void* p) {
    uint32_t a;
    asm("{ .reg .u64 t; cvta.to.shared.u64 t, %1; cvt.u32.u64 %0, t; }"
        : "=r"(a) : "l"(p));
    return a;
}
__device__ __forceinline__ uint32_t phys(uint32_t r, uint32_t c) {
    return r * 128u + ((c ^ (r & 7u)) << 4);
}
__device__ __forceinline__ void cp_async16(uint32_t s, const void* g) {
    asm volatile("cp.async.cg.shared.global [%0], [%1], 16;" :: "r"(s), "l"(g));
}
__device__ __forceinline__ void ldsm_x4(uint32_t addr, uint32_t& r0, uint32_t& r1,
                                        uint32_t& r2, uint32_t& r3) {
    asm volatile("ldmatrix.sync.aligned.m8n8.x4.shared.b16 {%0,%1,%2,%3}, [%4];"
                 : "=r"(r0), "=r"(r1), "=r"(r2), "=r"(r3) : "r"(addr));
}
__device__ __forceinline__ void hmma(float* c, const uint32_t* a, const uint32_t* b) {
    asm volatile(
        "mma.sync.aligned.m16n8k16.row.col.f32.f16.f16.f32 "
        "{%0,%1,%2,%3}, {%4,%5,%6,%7}, {%8,%9}, {%0,%1,%2,%3};"
        : "+f"(c[0]), "+f"(c[1]), "+f"(c[2]), "+f"(c[3])
        : "r"(a[0]), "r"(a[1]), "r"(a[2]), "r"(a[3]), "r"(b[0]), "r"(b[1]));
}
__device__ __forceinline__ unsigned short h_bits(__half h) {
    return *reinterpret_cast<unsigned short*>(&h);
}

// ---------------- conversions ------------------------------------------------
// g_A row: [Xhi (4096) | Xlo (4096)]
__global__ void __launch_bounds__(256) convert_x(const float* __restrict__ x) {
    size_t idx = (size_t)blockIdx.x * blockDim.x + threadIdx.x;
    int m = (int)(idx / (KD / 4));
    int k = (int)(idx % (KD / 4)) * 4;
    float4 v = *(const float4*)(x + (size_t)m * KD + k);
    float f[4] = {v.x, v.y, v.z, v.w};
    unsigned short hb[4], lb[4];
#pragma unroll
    for (int j = 0; j < 4; j++) {
        __half h = __float2half_rn(f[j]);
        hb[j] = h_bits(h);
        lb[j] = h_bits(__float2half_rn(f[j] - __half2float(h)));
    }
    ushort4* row = (ushort4*)(g_A + (size_t)m * K2);
    row[k / 4]        = make_ushort4(hb[0], hb[1], hb[2], hb[3]);
    row[(KD + k) / 4] = make_ushort4(lb[0], lb[1], lb[2], lb[3]);
}

// g_B row: [Whi | Wlo], W_sim = mask ? w : sign(w)*scale.
// Mask dtype detected per-CTA from the first 8KB (L2-broadcast, deterministic).
__global__ void __launch_bounds__(256) convert_w(const float* __restrict__ w,
                                                 const void* __restrict__ mask,
                                                 const float* __restrict__ bscale) {
    // ---- in-CTA mask dtype vote ----
    int lb_ = 0, lf_ = 0;
    {
        const unsigned int* mw = (const unsigned int*)mask;
        for (int i = threadIdx.x; i < 2048; i += 256) {
            unsigned int v = mw[i];
            if (v == 0x3F800000u)        lf_ = 1;
            else if (v != 0u && v != 1u) lb_ = 1;
        }
    }
    int isbyte  = __syncthreads_or(lb_);
    int isfloat = __syncthreads_or(lf_);
    const int mode = isbyte ? 0 : (isfloat ? 2 : 1);

    size_t idx = (size_t)blockIdx.x * blockDim.x + threadIdx.x;
    int n = (int)(idx / (KD / 4));
    int k = (int)(idx % (KD / 4)) * 4;
    size_t base = (size_t)n * KD + k;
    float4 v = *(const float4*)(w + base);
    const float scale = bscale[0];

    bool mk[4];
    if (mode == 0) {
        uchar4 mv = *(const uchar4*)((const unsigned char*)mask + base);
        mk[0] = mv.x != 0; mk[1] = mv.y != 0; mk[2] = mv.z != 0; mk[3] = mv.w != 0;
    } else if (mode == 1) {
        int4 mv = *(const int4*)((const int*)mask + base);
        mk[0] = mv.x != 0; mk[1] = mv.y != 0; mk[2] = mv.z != 0; mk[3] = mv.w != 0;
    } else {
        float4 mv = *(const float4*)((const float*)mask + base);
        mk[0] = mv.x != 0.f; mk[1] = mv.y != 0.f; mk[2] = mv.z != 0.f; mk[3] = mv.w != 0.f;
    }

    float f[4] = {v.x, v.y, v.z, v.w};
    unsigned short hb[4], lb2[4];
#pragma unroll
    for (int j = 0; j < 4; j++) {
        float s = (f[j] > 0.f) ? scale : ((f[j] < 0.f) ? -scale : 0.f);
        float ws = mk[j] ? f[j] : s;
        __half h = __float2half_rn(ws);
        hb[j]  = h_bits(h);
        lb2[j] = h_bits(__float2half_rn(ws - __half2float(h)));
    }
    ushort4* row = (ushort4*)(g_B + (size_t)n * K2);
    row[k / 4]        = make_ushort4(hb[0], hb[1], hb[2], hb[3]);
    row[(KD + k) / 4] = make_ushort4(lb2[0], lb2[1], lb2[2], lb2[3]);
}

// ---------------- GEMM: C = A_sim @ B_sim^T + bias --------------------------
// Logical K = 12288 via 3 segments over stored [hi|lo]:
//   seg0: Ahi*Bhi   seg1: Ahi*Blo   seg2: Alo*Bhi   (lo*lo dropped, ~2^-22)
// 256x128 CTA tile, BK=64, 8 warps (4x2), 64x64 warp tiles, 4-stage cp.async,
// ks-level register double buffering.
__global__ void __launch_bounds__(256, 1)
gemm_hmma(const float* __restrict__ bias, float* __restrict__ C) {
    extern __shared__ char smem[];
    const uint32_t sb = smem_u32(smem);
    const int tid  = threadIdx.x;
    const int lane = tid & 31;
    const int warp = tid >> 5;
    const int wm = warp >> 1;
    const int wn = warp & 1;

    // CTA raster swizzle: groups of 8 n-tiles, m-major inside group
    int bid = blockIdx.x;
    int bm, bn;
    const int FULLG = (NT / 8) * 8 * MT;    // 2560
    if (bid < FULLG) {
        int g = bid >> 8;
        int r = bid & 255;
        bn = g * 8 + (r & 7);
        bm = r >> 3;
    } else {
        int r = bid - FULLG;
        const int REM = NT % 8;             // 6
        bn = (NT / 8) * 8 + r % REM;
        bm = r / REM;
    }
    const int m0 = bm * BM, n0 = bn * BN;

    const __half* gA = g_A + (size_t)m0 * K2;
    const __half* gB = g_B + (size_t)n0 * K2;

    float acc[4][8][4];
#pragma unroll
    for (int i = 0; i < 4; i++)
#pragma unroll
        for (int j = 0; j < 8; j++)
#pragma unroll
            for (int t = 0; t < 4; t++) acc[i][j][t] = 0.f;

    auto load_stage = [&](int st, int it) {
        const uint32_t Ast = sb + st * STAGE_BYTES;
        const uint32_t Bst = Ast + BM * 128;
        const int kb = (it & 63) * BK;                       // elem offset in segment
        const size_t aoff = (it < 128) ? kb : (KD + kb);     // seg2 -> Alo
        const size_t boff = (it >= 64 && it < 128) ? (KD + kb) : kb;  // seg1 -> Blo
#pragma unroll
        for (int i = 0; i < 8; i++) {
            int ch = tid + i * 256;
            uint32_t r = ch >> 3, c = ch & 7;
            cp_async16(Ast + phys(r, c), gA + (size_t)r * K2 + aoff + c * 8);
        }
#pragma unroll
        for (int i = 0; i < 4; i++) {
            int ch = tid + i * 256;
            uint32_t r = ch >> 3, c = ch & 7;
            cp_async16(Bst + phys(r, c), gB + (size_t)r * K2 + boff + c * 8);
        }
        asm volatile("cp.async.commit_group;" ::: "memory");
    };

    load_stage(0, 0);
    load_stage(1, 1);
    load_stage(2, 2);

    const uint32_t lrow = lane & 15;
    const uint32_t lhik = lane >> 4;

    uint32_t a[2][4][4], b[2][8][2];

    auto load_frag = [&](uint32_t Ast, uint32_t Bst, int ks, int buf) {
#pragma unroll
        for (int mi = 0; mi < 4; mi++) {
            uint32_t r = wm * 64 + mi * 16 + lrow;
            ldsm_x4(Ast + phys(r, ks * 2 + lhik),
                    a[buf][mi][0], a[buf][mi][1], a[buf][mi][2], a[buf][mi][3]);
        }
#pragma unroll
        for (int nj = 0; nj < 4; nj++) {
            uint32_t r = wn * 64 + nj * 16 + lrow;
            uint32_t r0, r1, r2, r3;
            ldsm_x4(Bst + phys(r, ks * 2 + lhik), r0, r1, r2, r3);
            b[buf][2 * nj][0] = r0;     b[buf][2 * nj][1] = r2;
            b[buf][2 * nj + 1][0] = r1; b[buf][2 * nj + 1][1] = r3;
        }
    };

    for (int it = 0; it < NIT; it++) {
        asm volatile("cp.async.wait_group 2;" ::: "memory");
        __syncthreads();

        if (it + 3 < NIT) load_stage((it + 3) % STAGES, it + 3);
        else              asm volatile("cp.async.commit_group;" ::: "memory");

        const uint32_t Ast = sb + (it % STAGES) * STAGE_BYTES;
        const uint32_t Bst = Ast + BM * 128;

        load_frag(Ast, Bst, 0, 0);
#pragma unroll
        for (int ks = 0; ks < 4; ks++) {
            if (ks < 3) load_frag(Ast, Bst, ks + 1, (ks + 1) & 1);
            const int cur = ks & 1;
#pragma unroll
            for (int mi = 0; mi < 4; mi++)
#pragma unroll
                for (int nf = 0; nf < 8; nf++)
                    hmma(acc[mi][nf], a[cur][mi], b[cur][nf]);
        }
    }

    // ---- epilogue: bias + fp32 store ----
    const int mb = m0 + wm * 64;
    const int nb = n0 + wn * 64;
    float2 bv[8];
#pragma unroll
    for (int nf = 0; nf < 8; nf++)
        bv[nf] = *(const float2*)(bias + nb + nf * 8 + (lane & 3) * 2);
#pragma unroll
    for (int mi = 0; mi < 4; mi++) {
        int row = mb + mi * 16 + (lane >> 2);
#pragma unroll
        for (int nf = 0; nf < 8; nf++) {
            int col = nb + nf * 8 + (lane & 3) * 2;
            float2 o0 = {acc[mi][nf][0] + bv[nf].x, acc[mi][nf][1] + bv[nf].y};
            float2 o1 = {acc[mi][nf][2] + bv[nf].x, acc[mi][nf][3] + bv[nf].y};
            *(float2*)(C + (size_t)row * ND + col)       = o0;
            *(float2*)(C + (size_t)(row + 8) * ND + col) = o1;
        }
    }
}

// ---------------------------------------------------------------------------
extern "C" void kernel_launch(void* const* d_in, const int* in_sizes, int n_in,
                              void* d_out, int out_size) {
    const float* x      = (const float*)d_in[0];
    const float* weight = (const float*)d_in[1];
    const float* bias   = (const float*)d_in[2];
    const void*  mask   = d_in[3];
    const float* bscale = (const float*)d_in[4];
    float* out = (float*)d_out;

    convert_x<<<(MD * (KD / 4)) / 256, 256>>>(x);
    convert_w<<<(ND * (KD / 4)) / 256, 256>>>(weight, mask, bscale);

    static int smem_set = 0;
    if (!smem_set) {
        cudaFuncSetAttribute(gemm_hmma, cudaFuncAttributeMaxDynamicSharedMemorySize,
                             SMEM_BYTES);
        smem_set = 1;
    }
    gemm_hmma<<<NT * MT, 256, SMEM_BYTES>>>(bias, out);
}